// round 6
// baseline (speedup 1.0000x reference)
#include <cuda_runtime.h>
#include <cstdint>

#define TT 32     // simulation length
#define LL 4      // number of cores
#define BB 128    // batch
#define HH 1024   // neurons/axons per core

__device__ unsigned g_bitsA[BB * HH];
__device__ unsigned g_bitsB[BB * HH];

// ---------------------------------------------------------------------------
// Spike encoding: bit-exact fp32 mirror of to_uniform_spikes.
// ---------------------------------------------------------------------------
__global__ void encode_kernel(const float* __restrict__ x, unsigned* __restrict__ U)
{
    int idx = blockIdx.x * blockDim.x + threadIdx.x;
    if (idx >= BB * HH) return;
    float xv = x[idx];
    float Nf = rintf(__fmul_rn(xv, 32.0f));
    int   N  = (int)Nf;
    unsigned bits = 0u;
    if (N >= TT) {
        bits = 0xFFFFFFFFu;
    } else if (N > 0) {
        float spacing = __fdiv_rn(32.0f, (float)N);
        float fN = (float)N;
        #pragma unroll
        for (int t = 0; t < TT; ++t) {
            float c = (float)t;
            float q = floorf(__fdiv_rn(c, spacing));
            float r = fmodf(c, spacing);         // exact remainder (matches lax.rem)
            if (q < fN && floorf(r) == 0.0f) bits |= (1u << t);
        }
    }
    U[idx] = bits;
}

// ---------------------------------------------------------------------------
// One layer. CORRECTNESS-CRITICAL invariant: for every (b, n, t), z[t] is
// accumulated as a SINGLE fp32 accumulator over axons a in STRICT ASCENDING
// order. Do not reassociate, split accumulators, or reorder the a loop.
//
// Each thread owns FOUR neurons: n = nbase + lane + {0,32,64,96}. All four
// share the same warp-uniform spike mask u and its bit tests, so the
// per-active-bit branch machinery is amortized over 4 FADDs.
//
// smem weights are n-major: sW[n_local][a_local] with pad 33:
//   - inner-loop scalar LDS at [lane + p*32][a]: lane stride 33 == 1 mod 32,
//     conflict-free;
//   - staging: LDG.128 into registers, then FOUR SCALAR STS (pad 33 makes
//     rows only 4B-aligned, so STS.128 would fault -> R5 'misaligned
//     address'). Scalar STS banks (wn + 4*wa4 + j) mod 32 are conflict-free.
//
// Block = 128 threads = 4 b-rows x 32 lanes. Warp <-> one b row -> u is
// warp-uniform, branches never diverge.
// ---------------------------------------------------------------------------
template<int LAST>
__global__ void __launch_bounds__(128) layer_kernel(
    const unsigned* __restrict__ Uin,
    const float*    __restrict__ W,        // (HH neurons, HH axons) row-major
    const float*    __restrict__ thresholds,
    int layer,
    unsigned* __restrict__ Uout,
    float*    __restrict__ out)
{
    __shared__ float    sW[128][33];  // [n_local][a_local], pad 33
    __shared__ unsigned sU[4][32];    // [b_local][a_local]

    const int tx    = threadIdx.x;
    const int lane  = tx & 31;
    const int row   = tx >> 5;        // b within tile == warp id
    const int nbase = blockIdx.x * 128;
    const int bbase = blockIdx.y * 4;
    const int b     = bbase + row;
    const float thr = thresholds[layer];

    float z0[TT], z1[TT], z2[TT], z3[TT];
    #pragma unroll
    for (int t = 0; t < TT; ++t) { z0[t] = 0.0f; z1[t] = 0.0f; z2[t] = 0.0f; z3[t] = 0.0f; }

    for (int a0 = 0; a0 < HH; a0 += 32) {
        // Stage W tile: 128 n x 32 a. Each thread: 8x (LDG.128 + 4 scalar STS).
        #pragma unroll
        for (int i = 0; i < 8; ++i) {
            int lin = tx + i * 128;
            int wn  = lin >> 3;               // 0..127
            int wa4 = lin & 7;                // float4 column index
            float4 v = *reinterpret_cast<const float4*>(
                &W[(size_t)(nbase + wn) * HH + (a0 + wa4 * 4)]);
            sW[wn][wa4 * 4 + 0] = v.x;        // scalar stores: 4B-aligned OK,
            sW[wn][wa4 * 4 + 1] = v.y;        // banks conflict-free (see above)
            sW[wn][wa4 * 4 + 2] = v.z;
            sW[wn][wa4 * 4 + 3] = v.w;
        }
        // Stage spike masks: 4 b x 32 a (one word per thread)
        sU[row][lane] = Uin[(bbase + row) * HH + (a0 + lane)];
        __syncthreads();

        #pragma unroll 4
        for (int a = 0; a < 32; ++a) {          // ascending a: required for exactness
            unsigned u = sU[row][a];            // warp-uniform (LDS broadcast)
            if (u == 0u) continue;              // exact no-op
            float w0 = sW[lane      ][a];       // conflict-free scalar LDS x4,
            float w1 = sW[lane + 32 ][a];       // loaded ONCE per axon, reused
            float w2 = sW[lane + 64 ][a];       // across all 32 t-bits
            float w3 = sW[lane + 96 ][a];
            #pragma unroll
            for (int t = 0; t < TT; ++t) {
                if (u & (1u << t)) {            // one test feeds four chains
                    z0[t] += w0;
                    z1[t] += w1;
                    z2[t] += w2;
                    z3[t] += w3;
                }
            }
        }
        __syncthreads();
    }

    // LIF recurrence over 32 cycles, all in registers.
    float m0 = 0.0f, m1 = 0.0f, m2 = 0.0f, m3 = 0.0f;
    unsigned bits0 = 0u, bits1 = 0u, bits2 = 0u, bits3 = 0u;
    #pragma unroll
    for (int t = 0; t < TT; ++t) {
        m0 = __fadd_rn(m0, z0[t]);
        if (thr < m0) { m0 = __fsub_rn(m0, thr); bits0 |= (1u << t); }
        m1 = __fadd_rn(m1, z1[t]);
        if (thr < m1) { m1 = __fsub_rn(m1, thr); bits1 |= (1u << t); }
        m2 = __fadd_rn(m2, z2[t]);
        if (thr < m2) { m2 = __fsub_rn(m2, thr); bits2 |= (1u << t); }
        m3 = __fadd_rn(m3, z3[t]);
        if (thr < m3) { m3 = __fsub_rn(m3, thr); bits3 |= (1u << t); }
    }

    const int n0 = nbase + lane;
    if (LAST) {
        out[b * HH + n0     ] = (float)__popc(bits0) * (1.0f / 32.0f);
        out[b * HH + n0 + 32] = (float)__popc(bits1) * (1.0f / 32.0f);
        out[b * HH + n0 + 64] = (float)__popc(bits2) * (1.0f / 32.0f);
        out[b * HH + n0 + 96] = (float)__popc(bits3) * (1.0f / 32.0f);
    } else {
        Uout[b * HH + n0     ] = bits0;
        Uout[b * HH + n0 + 32] = bits1;
        Uout[b * HH + n0 + 64] = bits2;
        Uout[b * HH + n0 + 96] = bits3;
    }
}

// ---------------------------------------------------------------------------
// Launch: encode -> 4 layer passes (ping-pong bitmask buffers).
// ---------------------------------------------------------------------------
extern "C" void kernel_launch(void* const* d_in, const int* in_sizes, int n_in,
                              void* d_out, int out_size)
{
    const float* x   = (const float*)d_in[0];                 // (128,1024)
    const float* Wts = (const float*)d_in[1];                 // (4,1024,1024)
    const float* thr = (const float*)d_in[2];                 // (4,)
    float* out = (float*)d_out;                               // (128,1024)

    static unsigned* pA = nullptr;
    static unsigned* pB = nullptr;
    if (!pA) {
        cudaGetSymbolAddress((void**)&pA, g_bitsA);
        cudaGetSymbolAddress((void**)&pB, g_bitsB);
    }

    encode_kernel<<<(BB * HH + 255) / 256, 256>>>(x, pA);

    dim3 grid(HH / 128, BB / 4);   // (8, 32) = 256 blocks of 128 threads
    const size_t Wstride = (size_t)HH * HH;

    layer_kernel<0><<<grid, 128>>>(pA, Wts + 0 * Wstride, thr, 0, pB, nullptr);
    layer_kernel<0><<<grid, 128>>>(pB, Wts + 1 * Wstride, thr, 1, pA, nullptr);
    layer_kernel<0><<<grid, 128>>>(pA, Wts + 2 * Wstride, thr, 2, pB, nullptr);
    layer_kernel<1><<<grid, 128>>>(pB, Wts + 3 * Wstride, thr, 3, nullptr, out);
}